// round 16
// baseline (speedup 1.0000x reference)
#include <cuda_runtime.h>
#include <cuda_bf16.h>
#include <cuda_fp16.h>
#include <math.h>
#include <cstdint>

// Problem dims
#define TGT   64
#define SRC   64
#define BATCH 32
#define HID   512
#define ATT   512

// Scratch (no cudaMalloc allowed)
__device__ float g_hpart[TGT * BATCH * ATT];   // [t*BATCH+b][a]
__device__ float g_spart[SRC * BATCH * ATT];   // [s*BATCH+b][a]
__device__ __align__(16) __half g_Ah[2 * TGT * BATCH * HID]; // fp16 [h_t|src]
__device__ __align__(16) __half g_Bh[2 * HID * ATT];         // fp16 Wa^T: [z][n][k]
__device__ __align__(16) __half g_SrcT[BATCH * HID * SRC];   // fp16 src^T: [b][h][s]

// ---------------------------------------------------------------------------
// helpers
// ---------------------------------------------------------------------------
__device__ __forceinline__ float tanh_fast(float x) {
    float y;
    asm("tanh.approx.f32 %0, %1;" : "=f"(y) : "f"(x));
    return y;
}
__device__ __forceinline__ uint32_t smem_u32(const void* p) {
    uint32_t a;
    asm("{ .reg .u64 t; cvta.to.shared.u64 t, %1; cvt.u32.u64 %0, t; }"
        : "=r"(a) : "l"(p));
    return a;
}
#define CP_ASYNC16(dst, srcp) \
    asm volatile("cp.async.cg.shared.global [%0], [%1], 16;" :: "r"(dst), "l"(srcp))
#define CP_COMMIT() asm volatile("cp.async.commit_group;" ::: "memory")
#define CP_WAIT1()  asm volatile("cp.async.wait_group 1;" ::: "memory")
#define CP_WAIT0()  asm volatile("cp.async.wait_group 0;" ::: "memory")

#define LDSM_X4(r, addr)                                                       \
    asm volatile("ldmatrix.sync.aligned.m8n8.x4.shared.b16 {%0,%1,%2,%3}, [%4];" \
        : "=r"((r)[0]), "=r"((r)[1]), "=r"((r)[2]), "=r"((r)[3]) : "r"(addr))

// fp16 mma: D(f32) += A(f16) * B(f16), m16n8k16
__device__ __forceinline__ void mma_f16(float* c, const uint32_t* a, const uint32_t* b) {
    asm volatile(
        "mma.sync.aligned.m16n8k16.row.col.f32.f16.f16.f32 "
        "{%0,%1,%2,%3}, {%4,%5,%6,%7}, {%8,%9}, {%0,%1,%2,%3};"
        : "+f"(c[0]), "+f"(c[1]), "+f"(c[2]), "+f"(c[3])
        : "r"(a[0]), "r"(a[1]), "r"(a[2]), "r"(a[3]), "r"(b[0]), "r"(b[1]));
}

// ---------------------------------------------------------------------------
// Kernel 0: fp16 pre-pass. (R15, unchanged)
// ---------------------------------------------------------------------------
#define A4TOT (2 * TGT * BATCH * HID / 4)   // 524288 float4

__global__ __launch_bounds__(256) void prep_fp16(
    const float* __restrict__ h_t,
    const float* __restrict__ src,
    const float* __restrict__ Wa)
{
    const int bx  = blockIdx.x;
    const int tid = threadIdx.x;

    if (bx < 256) {
        for (int i = bx * 256 + tid; i < A4TOT; i += 256 * 256) {
            float4 v = (i < A4TOT / 2) ? ((const float4*)h_t)[i]
                                       : ((const float4*)src)[i - A4TOT / 2];
            __half2 lo = __float22half2_rn(make_float2(v.x, v.y));
            __half2 hi = __float22half2_rn(make_float2(v.z, v.w));
            uint2 pk;
            pk.x = *(uint32_t*)&lo;
            pk.y = *(uint32_t*)&hi;
            ((uint2*)g_Ah)[i] = pk;
        }
    } else if (bx < 768) {
        __shared__ float t[32][33];
        const int tile = bx - 256;            // 0..511
        const int z  = tile >> 8;
        const int rm = tile & 255;
        const int k0 = (rm & 15) * 32;
        const int n0 = (rm >> 4) * 32;
        const int tx = tid & 31, ty = tid >> 5;
#pragma unroll
        for (int r = 0; r < 32; r += 8)
            t[ty + r][tx] = Wa[(z * HID + k0 + ty + r) * ATT + n0 + tx];
        __syncthreads();
#pragma unroll
        for (int r = 0; r < 32; r += 8)
            g_Bh[z * HID * ATT + (n0 + ty + r) * HID + k0 + tx] =
                __float2half_rn(t[tx][ty + r]);
    } else {
        __shared__ float t[32][33];
        const int tile = bx - 768;            // 0..1023
        const int b  = tile >> 5;             // 0..31
        const int rm = tile & 31;
        const int s0 = (rm & 1) * 32;         // 0,32
        const int h0 = (rm >> 1) * 32;        // 0..480
        const int tx = tid & 31, ty = tid >> 5;
#pragma unroll
        for (int r = 0; r < 32; r += 8)
            t[ty + r][tx] = src[((s0 + ty + r) * BATCH + b) * HID + h0 + tx];
        __syncthreads();
#pragma unroll
        for (int r = 0; r < 32; r += 8)
            g_SrcT[(b * HID + h0 + ty + r) * SRC + s0 + tx] =
                __float2half_rn(t[tx][ty + r]);
    }
}

// ---------------------------------------------------------------------------
// Kernel 1: fp16 mma GEMM. (R14, unchanged — passing)
// ---------------------------------------------------------------------------
#define KTH    64
#define RSH    72
#define ASTGH  (128 * RSH)
#define BSTGH  (64 * RSH)
#define STGH   (ASTGH + BSTGH)

__global__ __launch_bounds__(256, 2) void gemm_mma_h(void)
{
    extern __shared__ __align__(16) __half smh[];
    const uint32_t smb = smem_u32(smh);

    const int tid  = threadIdx.x;
    const int lane = tid & 31;
    const int wid  = tid >> 5;
    const int g    = lane >> 2;
    const int tg   = lane & 3;

    const int wm = (wid >> 1) * 32;
    const int wn = (wid & 1) * 32;

    const int ntile = blockIdx.x;
    const int mtile = blockIdx.y;
    const int z  = mtile >> 4;
    const int m0 = (mtile & 15) * 128;
    const int n0 = ntile * 64;
    const __half* A = g_Ah + z * (TGT * BATCH * HID);
    const __half* B = g_Bh + z * (HID * ATT);
    float*        C = (z == 0) ? g_hpart : g_spart;

    const uint32_t aoff = (uint32_t)(((wm + (lane & 15)) * RSH + ((lane >> 4) << 3)) * 2);
    const uint32_t boff0 = (uint32_t)((ASTGH +
        (wn + (((lane >> 4) & 1) << 3) + (lane & 7)) * RSH + (((lane >> 3) & 1) << 3)) * 2);
    const uint32_t boff1 = boff0 + (uint32_t)(16 * RSH * 2);

    auto stage = [&](int s, int bufi) {
        const int kt = s * KTH;
        const uint32_t bufA = smb + (uint32_t)(bufi * STGH) * 2u;
        const uint32_t bufB = bufA + (uint32_t)ASTGH * 2u;
#pragma unroll
        for (int r = 0; r < 4; r++) {
            const int idx = r * 256 + tid;
            const int am = idx >> 3, ac = idx & 7;
            CP_ASYNC16(bufA + (uint32_t)(am * RSH + ac * 8) * 2u,
                       A + (m0 + am) * HID + kt + ac * 8);
        }
#pragma unroll
        for (int r = 0; r < 2; r++) {
            const int idx = r * 256 + tid;
            const int bn = idx >> 3, bc = idx & 7;
            CP_ASYNC16(bufB + (uint32_t)(bn * RSH + bc * 8) * 2u,
                       B + (n0 + bn) * HID + kt + bc * 8);
        }
    };

    float acc[2][4][4];
#pragma unroll
    for (int mi = 0; mi < 2; mi++)
#pragma unroll
        for (int ni = 0; ni < 4; ni++)
#pragma unroll
            for (int j = 0; j < 4; j++) acc[mi][ni][j] = 0.f;

    stage(0, 0); CP_COMMIT();
    stage(1, 1); CP_COMMIT();

    for (int s = 0; s < 8; s++) {
        if (s < 7) CP_WAIT1(); else CP_WAIT0();
        __syncthreads();
        if (s + 2 < 8) { stage(s + 2, (s + 2) % 3); CP_COMMIT(); }

        const uint32_t base = smb + (uint32_t)((s % 3) * STGH) * 2u;
#pragma unroll
        for (int ks = 0; ks < 4; ks++) {
            const uint32_t koff = (uint32_t)(ks * 32);
            uint32_t a[2][4], b2[2][4];
            LDSM_X4(a[0], base + aoff + koff);
            LDSM_X4(a[1], base + aoff + (uint32_t)(16 * RSH * 2) + koff);
            LDSM_X4(b2[0], base + boff0 + koff);
            LDSM_X4(b2[1], base + boff1 + koff);
#pragma unroll
            for (int mi = 0; mi < 2; mi++)
#pragma unroll
                for (int ni = 0; ni < 4; ni++)
                    mma_f16(acc[mi][ni], a[mi], &b2[ni >> 1][(ni & 1) * 2]);
        }
    }

#pragma unroll
    for (int mi = 0; mi < 2; mi++) {
#pragma unroll
        for (int ni = 0; ni < 4; ni++) {
            const int row = m0 + wm + mi * 16 + g;
            const int col = n0 + wn + ni * 8 + 2 * tg;
            *(float2*)(C + row * ATT + col)       = make_float2(acc[mi][ni][0], acc[mi][ni][1]);
            *(float2*)(C + (row + 8) * ATT + col) = make_float2(acc[mi][ni][2], acc[mi][ni][3]);
        }
    }
}

// ---------------------------------------------------------------------------
// Kernel 2: fused scores + softmax + context.
// Phase 1 (R12/R15, passing): block (8 t's, b); warp ti owns t; in-warp
// softmax -> attn fp16 in DEDICATED smem region (rows 8-15 zeroed).
// Phase 2 (R15-verified machinery): 4 h-chunks of 128 from g_SrcT [h][s],
// cp.async staged into the (fully consumed) phase-1 float region;
// non-trans ldmatrix A (attn, M=16 w/ 8 live rows) + B (srcT), m16n8k16;
// store only D rows 0-7.
// ---------------------------------------------------------------------------
#define SSTR 516
#define ATW  72     // attn smem stride (halves) — gemm-verified geometry
#define CTW  72     // srcT smem stride (halves)

__global__ __launch_bounds__(256) void scores_ctx_kernel(
    const float* __restrict__ Va,
    float* __restrict__ out)
{
    extern __shared__ float smem[];
    float* hs = smem;                 // 8  * SSTR
    float* ss = smem + 8 * SSTR;      // 16 * SSTR
    float* va = smem + 24 * SSTR;     // 512
    __half* at = (__half*)(smem + 24 * SSTR + 512);   // DEDICATED: 16*ATW halves

    const int b   = blockIdx.y;
    const int t0  = blockIdx.x * 8;
    const int tid = threadIdx.x;

    const int ti   = tid >> 5;
    const int lane = tid & 31;
    const int sh   = lane >> 4;
    const int sl   = lane & 15;
    const int aoff = sh * 256;

    va[tid]       = Va[tid];
    va[tid + 256] = Va[tid + 256];

    // zero attn rows 8-15 (ldsm reads them; D rows 8-15 discarded anyway)
    if (tid < 128) {
        const int r = tid >> 4, c = tid & 15;
        *(uint32_t*)(at + (8 + r) * ATW + c * 4) = 0u;
        *(uint32_t*)(at + (8 + r) * ATW + c * 4 + 2) = 0u;
    }

    // ---- phase 1: scores + softmax (unchanged) ----
#pragma unroll
    for (int r = 0; r < 4; r++) {
        int idx  = r * 256 + tid;
        int row  = idx >> 7;
        int col4 = idx & 127;
        float4 v = *(const float4*)(g_hpart + ((t0 + row) * BATCH + b) * ATT + col4 * 4);
        *(float4*)(hs + row * SSTR + col4 * 4) = v;
    }

    float sc[4];

#pragma unroll
    for (int c = 0; c < 4; c++) {
        __syncthreads();
#pragma unroll
        for (int r = 0; r < 8; r++) {
            int idx  = r * 256 + tid;
            int row  = idx >> 7;
            int col4 = idx & 127;
            float4 v = *(const float4*)(g_spart + ((c * 16 + row) * BATCH + b) * ATT + col4 * 4);
            *(float4*)(ss + row * SSTR + col4 * 4) = v;
        }
        __syncthreads();

        const float* hp = hs + ti * SSTR + aoff;
        const float* sp = ss + sl * SSTR + aoff;
        const float* vp = va + aoff;
        float acc = 0.f;
#pragma unroll 4
        for (int a = 0; a < 256; a += 4) {
            float4 h4 = *(const float4*)(hp + a);
            float4 s4 = *(const float4*)(sp + a);
            float4 v4 = *(const float4*)(vp + a);
            acc = fmaf(tanh_fast(h4.x + s4.x), v4.x, acc);
            acc = fmaf(tanh_fast(h4.y + s4.y), v4.y, acc);
            acc = fmaf(tanh_fast(h4.z + s4.z), v4.z, acc);
            acc = fmaf(tanh_fast(h4.w + s4.w), v4.w, acc);
        }
        sc[c] = acc;
    }

#pragma unroll
    for (int c = 0; c < 4; c++)
        sc[c] += __shfl_xor_sync(0xffffffffu, sc[c], 16);

    float mx = fmaxf(fmaxf(sc[0], sc[1]), fmaxf(sc[2], sc[3]));
#pragma unroll
    for (int o = 1; o <= 8; o <<= 1)
        mx = fmaxf(mx, __shfl_xor_sync(0xffffffffu, mx, o));

    float e[4], sum = 0.f;
#pragma unroll
    for (int c = 0; c < 4; c++) { e[c] = __expf(sc[c] - mx); sum += e[c]; }
#pragma unroll
    for (int o = 1; o <= 8; o <<= 1)
        sum += __shfl_xor_sync(0xffffffffu, sum, o);
    const float inv = 1.0f / sum;

    // attn fp16 -> dedicated smem region (warp ti = row ti)
    if (sh == 0) {
#pragma unroll
        for (int c = 0; c < 4; c++)
            at[ti * ATW + c * 16 + sl] = __float2half_rn(e[c] * inv);
    }

    // ---- phase 2: context via fp16 mma (non-trans ldmatrix) ----
    const uint32_t atb = smem_u32(at);
    const uint32_t stb = smem_u32(smem);   // reuse hs/ss float region (consumed)

    // fragment lane offsets — exact gemm-verified formulas
    const uint32_t afo = atb + (uint32_t)(((lane & 15) * ATW + ((lane >> 4) << 3)) * 2);
    const int wn = ti * 16;                 // warp n-slice (16 h of the 128 chunk)
    const uint32_t bfo = stb + (uint32_t)(((wn + (((lane >> 4) & 1) << 3) + (lane & 7)) * CTW
                                           + (((lane >> 3) & 1) << 3)) * 2);

    const int g  = lane >> 2;
    const int tg = lane & 3;
    const __half* st = g_SrcT + b * (HID * SRC);

#pragma unroll
    for (int hcc = 0; hcc < 4; hcc++) {
        const int h0c = hcc * 128;
        __syncthreads();   // phase-1 reads / prior chunk mma complete; attn visible (1st)
        // stage srcT chunk [128 h][64 s]: 1024 16B-chunks, 4/thread
#pragma unroll
        for (int r = 0; r < 4; r++) {
            const int idx = r * 256 + tid;
            const int row = idx >> 3, c = idx & 7;
            CP_ASYNC16(stb + (uint32_t)(row * CTW + c * 8) * 2u,
                       st + (h0c + row) * SRC + c * 8);
        }
        CP_COMMIT(); CP_WAIT0();
        __syncthreads();

        float acc[2][4];
#pragma unroll
        for (int ni = 0; ni < 2; ni++)
#pragma unroll
            for (int j = 0; j < 4; j++) acc[ni][j] = 0.f;

#pragma unroll
        for (int ks = 0; ks < 4; ks++) {
            const uint32_t koff = (uint32_t)(ks * 32);   // 16 halves
            uint32_t a[4], b4[4];
            LDSM_X4(a, afo + koff);
            LDSM_X4(b4, bfo + koff);
            mma_f16(acc[0], a, &b4[0]);
            mma_f16(acc[1], a, &b4[2]);
        }

        // store D rows 0-7 only (t = t0 + g, g in 0..7)
        const int t   = t0 + g;
        const int col = h0c + wn + 2 * tg;
        *(float2*)(out + (t * BATCH + b) * HID + col)     = make_float2(acc[0][0], acc[0][1]);
        *(float2*)(out + (t * BATCH + b) * HID + col + 8) = make_float2(acc[1][0], acc[1][1]);
    }
}

// ---------------------------------------------------------------------------
extern "C" void kernel_launch(void* const* d_in, const int* in_sizes, int n_in,
                              void* d_out, int out_size)
{
    const float* h_t  = (const float*)d_in[0];   // (64, 32, 512)
    const float* srce = (const float*)d_in[1];   // (64, 32, 512)
    const float* Wa   = (const float*)d_in[2];   // (1024, 512)
    const float* Va   = (const float*)d_in[3];   // (512,)
    float* out = (float*)d_out;                  // (64, 32, 512)

    (void)in_sizes; (void)n_in; (void)out_size;

    // 0) fp16 pre-pass: A convert + W transpose + src transpose
    prep_fp16<<<1792, 256>>>(h_t, srce, Wa);

    // 1) fp16 GEMMs (ldmatrix): grid (8 n, 32 m) = 256 CTAs, 2/SM
    const int gemm_smem = 3 * STGH * (int)sizeof(__half);   // 82944 B
    cudaFuncSetAttribute(gemm_mma_h,
                         cudaFuncAttributeMaxDynamicSharedMemorySize, gemm_smem);
    gemm_mma_h<<<dim3(8, 32), 256, gemm_smem>>>();

    // 2) fused scores + softmax + context: grid (8 t-tiles, 32 b) = 256 blocks
    const int sc_smem = (24 * SSTR + 512) * (int)sizeof(float)
                      + 16 * ATW * (int)sizeof(__half);     // 53888 B
    cudaFuncSetAttribute(scores_ctx_kernel,
                         cudaFuncAttributeMaxDynamicSharedMemorySize, sc_smem);
    scores_ctx_kernel<<<dim3(8, 32), 256, sc_smem>>>(Va, out);
}